// round 12
// baseline (speedup 1.0000x reference)
#include <cuda_runtime.h>

typedef unsigned long long u64;

#define HW   64
#define F    64
#define D    75
#define KR   5
#define NROW 15
#define SXW  68          // full row + 4 halo
#define NTHR 256

// u64 offsets
#define WPU  0           // WP pairs [75][33] u64 (stride-33 pad) = 2475
#define XPU  2476        // patch dup [15][68] u64 = 1020 (16B-aligned base)
#define SWU  3496        // w2 partials [8][32] u64 = 256
#define X2U  3752        // x2: 64 f32 = 32 u64
#define SMEM_U64 3784    // 30272 B
// f32 aliases over WP (dead after main loop)
#define FLO  0           // [64][33] f32 = 2112
#define FHI  2112        // [64][33] f32 (ends at f32 4224 = u64 2112 < 2475)

__global__ __launch_bounds__(NTHR, 4)
void euclid2d_kernel(const float* __restrict__ x,
                     const float* __restrict__ W,
                     float* __restrict__ out) {
    __shared__ __align__(16) u64 S[SMEM_U64];
    float* Sf = (float*)S;

    const int tid  = threadIdx.x;
    const int lane = tid & 31;
    const int w    = tid >> 5;        // warp 0..7 -> pixels w*8..w*8+7
    const int ho   = blockIdx.x;      // 0..63
    const int n    = blockIdx.y;      // 0..7

    // ---- patch tile (duplicated pairs), full 64-px row ----
    {
        const int y0 = ho - 2;
        #pragma unroll
        for (int k = 0; k < 4; k++) {
            int i = tid + k * NTHR;            // 0..1019
            if (i < NROW * SXW) {
                int row = i / SXW;
                int col = i % SXW;
                int gy = y0 + (row % KR);
                int gx = col - 2;
                float v = 0.0f;
                if (gy >= 0 && gy < HW && gx >= 0 && gx < HW)
                    v = x[((n * 3 + (row / KR)) * HW + gy) * HW + gx];
                u64 p;
                asm("mov.b64 %0, {%1, %1};" : "=l"(p) : "f"(v));
                S[XPU + i] = p;
            }
        }
    }

    // ---- direct W transpose: lane = d -> coalesced LDG, conflict-free STS.64 ----
    // tasks t = 0..95: fp = t & 31, dblk = t >> 5; warp w takes t ≡ w (mod 8)
    #pragma unroll
    for (int it = 0; it < 12; it++) {
        int t    = w + 8 * it;
        int fp   = t & 31;
        int dblk = t >> 5;
        int d    = dblk * 32 + lane;
        if (d < D) {
            float lo = W[(2 * fp)     * D + d];   // lane-consecutive
            float hi = W[(2 * fp + 1) * D + d];   // lane-consecutive
            u64 p;
            asm("mov.b64 %0, {%1, %2};" : "=l"(p) : "f"(lo), "f"(hi));
            S[WPU + d * 33 + fp] = p;             // stride-33: conflict-free
        }
    }
    __syncthreads();   // barrier 1: WP + patch ready

    // ---- x2 partials (4 thr/px, shfl) and w2 partials (8-way d-split) ----
    {
        const int px = tid >> 2;               // 0..63
        const int q  = tid & 3;
        float s = 0.0f;
        #pragma unroll
        for (int k = 0; k < 19; k++) {
            int d = q + 4 * k;
            if (d < D) {
                int row = d / KR, kw = d % KR;
                float v = Sf[(XPU + row * SXW + px + kw) * 2];
                s += v * v;
            }
        }
        s += __shfl_xor_sync(0xffffffffu, s, 1);
        s += __shfl_xor_sync(0xffffffffu, s, 2);
        if (q == 0) Sf[X2U * 2 + px] = s;
    }
    {
        int fp = tid & 31, q = tid >> 5;       // q = 0..7
        u64 a = 0ULL;
        #pragma unroll
        for (int k = 0; k < 10; k++) {
            int d = q + 8 * k;
            if (d < D) {
                u64 wv = S[WPU + d * 33 + fp];
                asm("fma.rn.f32x2 %0, %1, %1, %0;" : "+l"(a) : "l"(wv));
            }
        }
        S[SWU + q * 32 + fp] = a;
    }
    __syncthreads();   // barrier 2: partials ready

    // ---- main loop: lane = filter pair, thread = 8 pixels (FULL unroll) ----
    u64 acc[8];
    #pragma unroll
    for (int p = 0; p < 8; p++) acc[p] = 0ULL;

    #pragma unroll
    for (int row = 0; row < NROW; row++) {
        const ulonglong2* prow = (const ulonglong2*)&S[XPU + row * SXW + w * 8];
        ulonglong2 P2[6];
        #pragma unroll
        for (int t = 0; t < 6; t++) P2[t] = prow[t];        // broadcast LDS.128
        const u64* Pu = (const u64*)P2;                      // 12 u64
        #pragma unroll
        for (int kw = 0; kw < KR; kw++) {
            u64 wv = S[WPU + (row * KR + kw) * 33 + lane];   // conflict-free LDS.64
            #pragma unroll
            for (int p = 0; p < 8; p++)
                asm("fma.rn.f32x2 %0, %1, %2, %0;"
                    : "+l"(acc[p]) : "l"(Pu[kw + p]), "l"(wv));
        }
    }

    // ---- epilogue: w2 from 8 partials, res, padded transpose ----
    {
        u64 w2l = S[SWU + lane];
        #pragma unroll
        for (int q = 1; q < 8; q++) {
            u64 aq = S[SWU + q * 32 + lane];
            asm("add.rn.f32x2 %0, %0, %1;" : "+l"(w2l) : "l"(aq));
        }
        u64 nh;
        { float mh = -0.5f; asm("mov.b64 %0, {%1, %1};" : "=l"(nh) : "f"(mh)); }
        float x2v[8];
        #pragma unroll
        for (int p = 0; p < 8; p++) x2v[p] = Sf[X2U * 2 + w * 8 + p];
        __syncthreads();   // barrier 3: all WP/partial reads done before aliasing
        #pragma unroll
        for (int p = 0; p < 8; p++) {
            int px = w * 8 + p;
            u64 x2d, s, r = acc[p];
            asm("mov.b64 %0, {%1, %1};" : "=l"(x2d) : "f"(x2v[p]));
            asm("add.rn.f32x2 %0, %1, %2;" : "=l"(s) : "l"(x2d), "l"(w2l));
            asm("fma.rn.f32x2 %0, %1, %2, %0;" : "+l"(r) : "l"(s), "l"(nh));
            float lo, hi;
            asm("mov.b64 {%0, %1}, %2;" : "=f"(lo), "=f"(hi) : "l"(r));
            Sf[FLO + px * 33 + lane] = lo;    // conflict-free
            Sf[FHI + px * 33 + lane] = hi;
        }
    }
    __syncthreads();   // barrier 4: transpose buffer ready

    // ---- store: lane = pixel -> contiguous 128B runs ----
    #pragma unroll
    for (int k = 0; k < 4; k++) {
        int fp = w + 8 * k;
        float* o0 = out + (((long)(n * F + 2 * fp)     * HW + ho) * HW);
        float* o1 = out + (((long)(n * F + 2 * fp + 1) * HW + ho) * HW);
        #pragma unroll
        for (int half = 0; half < 2; half++) {
            int px = half * 32 + lane;
            o0[px] = Sf[FLO + px * 33 + fp];
            o1[px] = Sf[FHI + px * 33 + fp];
        }
    }
}

extern "C" void kernel_launch(void* const* d_in, const int* in_sizes, int n_in,
                              void* d_out, int out_size) {
    const float* x = (const float*)d_in[0];
    const float* W = (const float*)d_in[1];
    float* out = (float*)d_out;

    dim3 grid(HW, 8);    // 512 CTAs
    euclid2d_kernel<<<grid, NTHR>>>(x, W, out);
}